// round 7
// baseline (speedup 1.0000x reference)
#include <cuda_runtime.h>

#define B 4
#define L 2048
#define H 8
#define D 64
#define S 40
#define NTOP 40
#define BH (B*H)

#define KS 8            // k-splits for flash attention
#define KC (L/KS)       // 256 keys per split
#define KT 64           // tile rows
#define NTILE (KC/KT)   // 4 tiles per split

#define CCH 64          // cumsum chunks
#define CLEN (L/CCH)    // 32 rows per chunk
#define RPT 4           // cumsum rows per thread
#define SUBG (CLEN/RPT) // 8 subgroups

#define FULLMASK 0xffffffffu

// Scratch (no allocations allowed)
__device__ float g_M[BH * L];
__device__ int   g_top[BH * NTOP];
__device__ float g_cs[BH * CCH * D];
__device__ float g_pm[BH * NTOP * KS];
__device__ float g_pl[BH * NTOP * KS];
__device__ float g_pacc[BH * NTOP * KS * D];

__device__ __forceinline__ float4 f4add(float4 a, float4 b) {
    return make_float4(a.x + b.x, a.y + b.y, a.z + b.z, a.w + b.w);
}

// ---------------------------------------------------------------------------
// Kernel 1: M[bh,l] = max_s(Q[l]·K[idx[l,s]]) - (sum_s Q[l]·K[idx[l,s]]) / L
// One warp per (bh,l). Coalesced group-gather: 8 lanes per sample, 4 samples
// per step (nL=4 wavefronts per LDG.128). index_sample is int32 on the wire.
// ---------------------------------------------------------------------------
__global__ void __launch_bounds__(256)
mscore_kernel(const float* __restrict__ Q,
              const float* __restrict__ K,
              const int* __restrict__ idx) {
    int warp = blockIdx.x * 8 + (threadIdx.x >> 5);
    int lane = threadIdx.x & 31;
    int g = lane >> 3, j = lane & 7;
    int l  = warp & (L - 1);
    int bh = warp >> 11;
    int b = bh >> 3, h = bh & 7;

    const float4* q4 = (const float4*)(Q + ((size_t)(b * L + l) * H + h) * D);
    float4 qa = q4[j], qb = q4[8 + j];

    const int* srow = idx + (size_t)l * S;
    int s_lo = srow[lane];
    int s_hi = (lane < 8) ? srow[lane + 32] : 0;

    const float* Kb = K + ((size_t)b * L * H + h) * D;
    float mx = -1e30f, sm = 0.f;

    #pragma unroll
    for (int bt = 0; bt < 10; bt++) {
        int s = bt * 4 + g;
        int ki = (bt < 8) ? __shfl_sync(FULLMASK, s_lo, s)
                          : __shfl_sync(FULLMASK, s_hi, s - 32);
        const float4* k4 = (const float4*)(Kb + (size_t)ki * H * D);
        float4 ka = k4[j], kb = k4[8 + j];
        float d = qa.x*ka.x + qa.y*ka.y + qa.z*ka.z + qa.w*ka.w
                + qb.x*kb.x + qb.y*kb.y + qb.z*kb.z + qb.w*kb.w;
        d += __shfl_down_sync(FULLMASK, d, 4);
        d += __shfl_down_sync(FULLMASK, d, 2);
        d += __shfl_down_sync(FULLMASK, d, 1);
        if (j == 0) { mx = fmaxf(mx, d); sm += d; }
    }

    if (j != 0) { mx = -1e30f; sm = 0.f; }
    mx = fmaxf(mx, __shfl_xor_sync(FULLMASK, mx, 8));
    sm +=          __shfl_xor_sync(FULLMASK, sm, 8);
    mx = fmaxf(mx, __shfl_xor_sync(FULLMASK, mx, 16));
    sm +=          __shfl_xor_sync(FULLMASK, sm, 16);

    if (lane == 0) g_M[bh * L + l] = mx - sm * (1.0f / (float)L);
}

// ---------------------------------------------------------------------------
// Kernel 2: top-40 of M per (bh). 40 block-argmax passes, then emit the
// selected index SET sorted ASCENDING (output is order-invariant: the
// scatter maps each lu to its own attention row). Ascending order enables
// causal work-skipping in attn_flash.
// ---------------------------------------------------------------------------
__global__ void topk_kernel() {
    int bh = blockIdx.x;
    __shared__ float vals[L];
    __shared__ float wv[8];
    __shared__ int   wi[8];
    __shared__ int   sel[NTOP];
    int tid = threadIdx.x;  // 256

    for (int i = tid; i < L; i += 256) vals[i] = g_M[bh * L + i];
    __syncthreads();

    for (int t = 0; t < NTOP; t++) {
        float bv = -1e38f; int bi = 0;
        for (int i = tid; i < L; i += 256) {
            float v = vals[i];
            if (v > bv) { bv = v; bi = i; }
        }
        #pragma unroll
        for (int off = 16; off; off >>= 1) {
            float ov = __shfl_down_sync(FULLMASK, bv, off);
            int   oi = __shfl_down_sync(FULLMASK, bi, off);
            if (ov > bv || (ov == bv && oi < bi)) { bv = ov; bi = oi; }
        }
        if ((tid & 31) == 0) { wv[tid >> 5] = bv; wi[tid >> 5] = bi; }
        __syncthreads();
        if (tid == 0) {
            float fv = wv[0]; int fi = wi[0];
            #pragma unroll
            for (int w = 1; w < 8; w++)
                if (wv[w] > fv || (wv[w] == fv && wi[w] < fi)) { fv = wv[w]; fi = wi[w]; }
            sel[t] = fi;
            vals[fi] = -1e38f;
        }
        __syncthreads();
    }

    // rank-sort the 40 (distinct) indices ascending
    if (tid < NTOP) {
        int mine = sel[tid], r = 0;
        #pragma unroll
        for (int i = 0; i < NTOP; i++) r += (sel[i] < mine);
        g_top[bh * NTOP + r] = mine;
    }
}

// ---------------------------------------------------------------------------
// Kernel 3a: per-chunk sums of V. grid (CCH, BH), block 128 (8 subg x 16 f4).
// ---------------------------------------------------------------------------
__global__ void cumsumA_kernel(const float* __restrict__ V) {
    int c = blockIdx.x, bh = blockIdx.y;
    int b = bh >> 3, h = bh & 7;
    int tid = threadIdx.x, rg = tid >> 4, f4 = tid & 15;
    const int RS = H * D / 4;   // float4 stride between rows

    const float4* vb = (const float4*)(V + ((size_t)(b * L + c * CLEN + rg * RPT) * H + h) * D) + f4;
    float4 s = vb[0];
    #pragma unroll
    for (int i = 1; i < RPT; i++) s = f4add(s, vb[(size_t)i * RS]);

    __shared__ float4 sm[SUBG][16];
    sm[rg][f4] = s;
    __syncthreads();
    if (rg == 0) {
        float4 t = sm[0][f4];
        #pragma unroll
        for (int i = 1; i < SUBG; i++) t = f4add(t, sm[i][f4]);
        ((float4*)g_cs)[(bh * CCH + c) * 16 + f4] = t;
    }
}

// ---------------------------------------------------------------------------
// Kernel 3b: scan. grid (CCH, BH), block 128. Thread handles 4 rows (chain 4),
// smem prefix over 8 subgroups, distributed sum of preceding chunk-sums.
// ---------------------------------------------------------------------------
__global__ void cumsumC_kernel(const float* __restrict__ V, float* __restrict__ out) {
    int c = blockIdx.x, bh = blockIdx.y;
    int b = bh >> 3, h = bh & 7;
    int tid = threadIdx.x, rg = tid >> 4, f4 = tid & 15;
    const int RS = H * D / 4;

    const float4* vb = (const float4*)(V + ((size_t)(b * L + c * CLEN + rg * RPT) * H + h) * D) + f4;
    float4 v0 = vb[0], v1 = vb[RS], v2 = vb[2 * RS], v3 = vb[3 * RS];
    float4 p = f4add(f4add(v0, v1), f4add(v2, v3));

    __shared__ float4 sp[SUBG][16];
    __shared__ float4 sg[SUBG][16];
    sp[rg][f4] = p;

    // distributed sum of preceding chunk-sums
    float4 gacc = make_float4(0.f, 0.f, 0.f, 0.f);
    const float4* cs4 = (const float4*)g_cs + (size_t)bh * CCH * 16 + f4;
    for (int cc = rg; cc < c; cc += SUBG) gacc = f4add(gacc, cs4[cc * 16]);
    sg[rg][f4] = gacc;
    __syncthreads();

    float4 run = make_float4(0.f, 0.f, 0.f, 0.f);
    #pragma unroll
    for (int i = 0; i < SUBG; i++) {
        run = f4add(run, sg[i][f4]);
        if (i < 7 && i < rg) run = f4add(run, sp[i][f4]);
    }
    // note: loop adds sg[0..7] (global base) and sp[0..rg-1] (local prefix)
    if (rg == 7) { /* sp[7] never added as prefix */ }

    float4 o0 = f4add(run, v0);
    float4 o1 = f4add(o0, v1);
    float4 o2 = f4add(o1, v2);
    float4 o3 = f4add(o2, v3);

    float4* ob = (float4*)(out + ((size_t)bh * L + c * CLEN + rg * RPT) * D) + f4;
    ob[0] = o0; ob[16] = o1; ob[32] = o2; ob[48] = o3;
}

// ---------------------------------------------------------------------------
// Kernel 4: flash attention partials. grid (KS, BH), block 256 (8 warps).
// lus is ASCENDING: warp w owns u [5w,5w+5) with coherent lu range; whole
// warp skips score/softmax/PV for tiles beyond its lu_hi (causal skip).
// ---------------------------------------------------------------------------
__global__ void __launch_bounds__(256)
attn_flash_kernel(const float* __restrict__ Q,
                  const float* __restrict__ K,
                  const float* __restrict__ V) {
    int ks = blockIdx.x, bh = blockIdx.y;
    int b = bh >> 3, h = bh & 7;
    int tid = threadIdx.x, w = tid >> 5, lane = tid & 31;
    int u0 = w * 5;
    int kbase0 = ks * KC;

    __shared__ float  tileT[D][KT + 1];
    __shared__ float4 qs4[NTOP][16];
    __shared__ float4 ps4[NTOP][16];
    __shared__ int    lus[NTOP];

    if (tid < NTOP) lus[tid] = g_top[bh * NTOP + tid];
    __syncthreads();
    int lu_hi  = lus[u0 + 4];       // warp's max lu (ascending order)
    int lu_blk = lus[NTOP - 1];     // block max
    int span = lu_blk + 1 - kbase0;
    int ntl = (span >= KC) ? NTILE : ((span <= 0) ? 0 : (span + KT - 1) / KT);

    for (int i = tid; i < NTOP * 16; i += 256) {
        int u = i >> 4, cq = i & 15;
        qs4[u][cq] = ((const float4*)(Q + ((size_t)(b * L + lus[u]) * H + h) * D))[cq];
    }

    float m[5], lsum[5], acc0[5], acc1[5];
    #pragma unroll
    for (int iu = 0; iu < 5; iu++) { m[iu] = -1e30f; lsum[iu] = 0.f; acc0[iu] = 0.f; acc1[iu] = 0.f; }

    int lr = tid >> 2, lc = tid & 3;
    float* psf = (float*)ps4;
    int t0 = lane, t1 = lane + 32;

    for (int tt = 0; tt < ntl; tt++) {
        int kbase = kbase0 + tt * KT;
        bool act = (kbase <= lu_hi);    // warp-uniform

        __syncthreads();
        {   // K tile -> tileT
            const float4* kr = (const float4*)(K + ((size_t)(b * L + kbase + lr) * H + h) * D);
            #pragma unroll
            for (int j = 0; j < 4; j++) {
                float4 v = kr[lc + 4 * j];
                int dc = (lc + 4 * j) * 4;
                tileT[dc + 0][lr] = v.x; tileT[dc + 1][lr] = v.y;
                tileT[dc + 2][lr] = v.z; tileT[dc + 3][lr] = v.w;
            }
        }
        __syncthreads();

        if (act) {
            float s0[5], s1[5];
            #pragma unroll
            for (int iu = 0; iu < 5; iu++) { s0[iu] = 0.f; s1[iu] = 0.f; }
            #pragma unroll
            for (int d4 = 0; d4 < 16; d4++) {
                float k00 = tileT[d4*4+0][t0], k01 = tileT[d4*4+1][t0];
                float k02 = tileT[d4*4+2][t0], k03 = tileT[d4*4+3][t0];
                float k10 = tileT[d4*4+0][t1], k11 = tileT[d4*4+1][t1];
                float k12 = tileT[d4*4+2][t1], k13 = tileT[d4*4+3][t1];
                #pragma unroll
                for (int iu = 0; iu < 5; iu++) {
                    float4 q = qs4[u0 + iu][d4];
                    s0[iu] += q.x*k00 + q.y*k01 + q.z*k02 + q.w*k03;
                    s1[iu] += q.x*k10 + q.y*k11 + q.z*k12 + q.w*k13;
                }
            }

            int kg0 = kbase + t0, kg1 = kbase + t1;
            #pragma unroll
            for (int iu = 0; iu < 5; iu++) {
                int lu = lus[u0 + iu];
                float a = (kg0 <= lu) ? s0[iu] * 0.125f : -3e38f;
                float c = (kg1 <= lu) ? s1[iu] * 0.125f : -3e38f;
                float mt = fmaxf(a, c);
                #pragma unroll
                for (int off = 16; off; off >>= 1)
                    mt = fmaxf(mt, __shfl_xor_sync(FULLMASK, mt, off));
                float mn = fmaxf(m[iu], mt);
                float f  = __expf(m[iu] - mn);
                float p0 = __expf(a - mn), p1 = __expf(c - mn);
                float psum = p0 + p1;
                #pragma unroll
                for (int off = 16; off; off >>= 1)
                    psum += __shfl_xor_sync(FULLMASK, psum, off);
                lsum[iu] = lsum[iu] * f + psum;
                acc0[iu] *= f; acc1[iu] *= f;
                psf[(u0 + iu) * 64 + t0] = p0;
                psf[(u0 + iu) * 64 + t1] = p1;
                m[iu] = mn;
            }
            __syncwarp();
        }
        __syncthreads();

        {   // V tile -> tileT
            const float4* vr = (const float4*)(V + ((size_t)(b * L + kbase + lr) * H + h) * D);
            #pragma unroll
            for (int j = 0; j < 4; j++) {
                float4 v = vr[lc + 4 * j];
                int dc = (lc + 4 * j) * 4;
                tileT[dc + 0][lr] = v.x; tileT[dc + 1][lr] = v.y;
                tileT[dc + 2][lr] = v.z; tileT[dc + 3][lr] = v.w;
            }
        }
        __syncthreads();

        if (act) {
            #pragma unroll
            for (int t4 = 0; t4 < 16; t4++) {
                float v00 = tileT[lane][t4*4+0], v01 = tileT[lane][t4*4+1];
                float v02 = tileT[lane][t4*4+2], v03 = tileT[lane][t4*4+3];
                float v10 = tileT[lane+32][t4*4+0], v11 = tileT[lane+32][t4*4+1];
                float v12 = tileT[lane+32][t4*4+2], v13 = tileT[lane+32][t4*4+3];
                #pragma unroll
                for (int iu = 0; iu < 5; iu++) {
                    float4 p = ps4[u0 + iu][t4];
                    acc0[iu] += p.x*v00 + p.y*v01 + p.z*v02 + p.w*v03;
                    acc1[iu] += p.x*v10 + p.y*v11 + p.z*v12 + p.w*v13;
                }
            }
        }
    }

    #pragma unroll
    for (int iu = 0; iu < 5; iu++) {
        size_t base = (size_t)(bh * NTOP + u0 + iu) * KS + ks;
        g_pacc[base * D + lane]      = acc0[iu];
        g_pacc[base * D + lane + 32] = acc1[iu];
        if (lane == 0) { g_pm[base] = m[iu]; g_pl[base] = lsum[iu]; }
    }
}

// ---------------------------------------------------------------------------
// Kernel 5: combine KS partials per (bh,u), normalize, scatter into out.
// Empty partials (m=-1e30, l=0) contribute exp(-inf)=0.
// ---------------------------------------------------------------------------
__global__ void attn_combine_kernel(float* __restrict__ out) {
    int u = blockIdx.x, bh = blockIdx.y;
    int d = threadIdx.x;
    size_t base = (size_t)(bh * NTOP + u) * KS;

    float mv[KS], lv[KS];
    float mg = -3e38f;
    #pragma unroll
    for (int p = 0; p < KS; p++) {
        mv[p] = g_pm[base + p];
        lv[p] = g_pl[base + p];
        mg = fmaxf(mg, mv[p]);
    }
    float ltot = 0.f, acc = 0.f;
    #pragma unroll
    for (int p = 0; p < KS; p++) {
        float e = __expf(mv[p] - mg);
        ltot += lv[p] * e;
        acc  += g_pacc[(base + p) * D + d] * e;
    }
    int lu = g_top[bh * NTOP + u];
    out[((size_t)bh * L + lu) * D + d] = acc / ltot;
}

// ---------------------------------------------------------------------------
extern "C" void kernel_launch(void* const* d_in, const int* in_sizes, int n_in,
                              void* d_out, int out_size) {
    const float* Q   = (const float*)d_in[0];
    const float* K   = (const float*)d_in[1];
    const float* V   = (const float*)d_in[2];
    const int*   idx = (const int*)d_in[3];
    float*       out = (float*)d_out;

    mscore_kernel<<<BH * L / 8, 256>>>(Q, K, idx);
    topk_kernel  <<<BH, 256>>>();
    cumsumA_kernel<<<dim3(CCH, BH), SUBG * 16>>>(V);
    cumsumC_kernel<<<dim3(CCH, BH), SUBG * 16>>>(V, out);
    attn_flash_kernel<<<dim3(KS, BH), 256>>>(Q, K, V);
    attn_combine_kernel<<<dim3(NTOP, BH), D>>>(out);
}